// round 1
// baseline (speedup 1.0000x reference)
#include <cuda_runtime.h>

// Problem constants (B=1 fixed)
#define S_LEN   2048
#define HID     6144
#define QKV_OUT 6400   // HID + 2*128
#define NH      48
#define HD      128

// Scratch (no cudaMalloc allowed): qkv activations + attention output
__device__ float g_qkv [S_LEN * QKV_OUT];   // ~52.4 MB
__device__ float g_attn[S_LEN * HID];       // ~50.3 MB

// ---------------------------------------------------------------------------
// SGEMM: C[M,N] = A[M,K] * B[N,K]^T + bias[N]
// A row-major [M,K], B row-major [N,K] (both K-contiguous), fp32.
// 128x128 tile, BK=8, 256 threads, 8x8 micro-tile per thread.
// M%128==0, N%128==0, K%8==0 assumed (true for all three GEMMs here).
// ---------------------------------------------------------------------------
__global__ void __launch_bounds__(256, 2) sgemm_nt_bias(
    const float* __restrict__ A, const float* __restrict__ B,
    const float* __restrict__ bias, float* __restrict__ C,
    int M, int N, int K)
{
    __shared__ float As[8][128];
    __shared__ float Bs[8][128];

    const int tid = threadIdx.x;
    const int tx  = tid & 15;   // N direction (8 cols each)
    const int ty  = tid >> 4;   // M direction (8 rows each)

    const int block_m = blockIdx.y * 128;
    const int block_n = blockIdx.x * 128;

    float acc[8][8];
    #pragma unroll
    for (int i = 0; i < 8; i++)
        #pragma unroll
        for (int j = 0; j < 8; j++) acc[i][j] = 0.0f;

    // Loader mapping: each thread loads one float4 from A and one from B per BK step
    const int lr = tid >> 1;         // 0..127 (row within tile)
    const int lc = (tid & 1) * 4;    // 0 or 4 (col within BK)

    const float* Aptr = A + (long)(block_m + lr) * K + lc;
    const float* Bptr = B + (long)(block_n + lr) * K + lc;

    for (int k0 = 0; k0 < K; k0 += 8) {
        float4 av = *(const float4*)(Aptr + k0);
        float4 bv = *(const float4*)(Bptr + k0);
        As[lc + 0][lr] = av.x; As[lc + 1][lr] = av.y;
        As[lc + 2][lr] = av.z; As[lc + 3][lr] = av.w;
        Bs[lc + 0][lr] = bv.x; Bs[lc + 1][lr] = bv.y;
        Bs[lc + 2][lr] = bv.z; Bs[lc + 3][lr] = bv.w;
        __syncthreads();

        #pragma unroll
        for (int kk = 0; kk < 8; kk++) {
            float a[8], b[8];
            float4 a0 = *(const float4*)&As[kk][ty * 8];
            float4 a1 = *(const float4*)&As[kk][ty * 8 + 4];
            float4 b0 = *(const float4*)&Bs[kk][tx * 8];
            float4 b1 = *(const float4*)&Bs[kk][tx * 8 + 4];
            a[0]=a0.x; a[1]=a0.y; a[2]=a0.z; a[3]=a0.w;
            a[4]=a1.x; a[5]=a1.y; a[6]=a1.z; a[7]=a1.w;
            b[0]=b0.x; b[1]=b0.y; b[2]=b0.z; b[3]=b0.w;
            b[4]=b1.x; b[5]=b1.y; b[6]=b1.z; b[7]=b1.w;
            #pragma unroll
            for (int i = 0; i < 8; i++)
                #pragma unroll
                for (int j = 0; j < 8; j++)
                    acc[i][j] += a[i] * b[j];
        }
        __syncthreads();
    }

    // Epilogue: add bias, store
    #pragma unroll
    for (int i = 0; i < 8; i++) {
        const int row = block_m + ty * 8 + i;
        #pragma unroll
        for (int j = 0; j < 8; j += 4) {
            const int col = block_n + tx * 8 + j;
            float4 bvec = *(const float4*)&bias[col];
            float4 o;
            o.x = acc[i][j + 0] + bvec.x;
            o.y = acc[i][j + 1] + bvec.y;
            o.z = acc[i][j + 2] + bvec.z;
            o.w = acc[i][j + 3] + bvec.w;
            *(float4*)&C[(long)row * N + col] = o;
        }
    }
}

// ---------------------------------------------------------------------------
// MQA causal flash attention (single KV head shared by 48 Q heads).
// Grid: (S/BQ, NH). 256 threads, 4 threads per Q row (BQ=64), online softmax.
// Smem rows padded to 132 floats so banks rotate by 4 per row (conflict-free
// broadcast reads); PV loop rotates column index by row so the 8 rows of a
// warp hit 8 distinct bank groups.
// ---------------------------------------------------------------------------
#define BQ  64
#define BKV 32
#define QPAD 132   // HD + 4

__global__ void __launch_bounds__(256, 2) mqa_flash_kernel(
    const float* __restrict__ qkv, float* __restrict__ attn_out)
{
    extern __shared__ float sm[];
    float* q_s = sm;                          // [BQ][QPAD]
    float* k_s = q_s + BQ * QPAD;             // [BKV][QPAD]
    float* v_s = k_s + BKV * QPAD;            // [BKV][QPAD]
    float* p_s = v_s + BKV * QPAD;            // [BQ][33]

    const int h   = blockIdx.y;
    const int q0  = blockIdx.x * BQ;
    const int tid = threadIdx.x;
    const int row = tid >> 2;    // 0..63
    const int sub = tid & 3;     // 0..3 (owns dims [sub*32, sub*32+32))

    const float scale = 0.08838834764831845f;  // 1/sqrt(128)

    // Load Q tile, pre-scaled
    for (int i = tid; i < BQ * HD / 4; i += 256) {
        int r = i >> 5;             // /(HD/4)
        int c = (i & 31) * 4;
        float4 v4 = *(const float4*)&qkv[(long)(q0 + r) * QKV_OUT + h * HD + c];
        v4.x *= scale; v4.y *= scale; v4.z *= scale; v4.w *= scale;
        *(float4*)&q_s[r * QPAD + c] = v4;
    }

    float o[32];
    #pragma unroll
    for (int d = 0; d < 32; d++) o[d] = 0.0f;
    float m_run = -1e30f, l_run = 0.0f;

    const int kt_end = (q0 + BQ - 1) / BKV;   // inclusive
    for (int kt = 0; kt <= kt_end; kt++) {
        const int k0 = kt * BKV;
        __syncthreads();   // previous PV reads of k_s/v_s/p_s complete
        for (int i = tid; i < BKV * HD / 4; i += 256) {
            int r = i >> 5;
            int c = (i & 31) * 4;
            long base = (long)(k0 + r) * QKV_OUT;
            *(float4*)&k_s[r * QPAD + c] = *(const float4*)&qkv[base + HID + c];
            *(float4*)&v_s[r * QPAD + c] = *(const float4*)&qkv[base + HID + HD + c];
        }
        __syncthreads();

        // Scores: this thread handles columns c = j*4 + sub, j=0..7
        float s[8];
        #pragma unroll
        for (int j = 0; j < 8; j++) s[j] = 0.0f;
        const float* qrow = &q_s[row * QPAD];
        #pragma unroll 8
        for (int d4 = 0; d4 < HD; d4 += 4) {
            float4 qv = *(const float4*)(qrow + d4);
            #pragma unroll
            for (int j = 0; j < 8; j++) {
                const int c = j * 4 + sub;
                float4 kv = *(const float4*)&k_s[c * QPAD + d4];
                s[j] += qv.x * kv.x + qv.y * kv.y + qv.z * kv.z + qv.w * kv.w;
            }
        }
        // Causal mask
        #pragma unroll
        for (int j = 0; j < 8; j++) {
            const int c = j * 4 + sub;
            if (k0 + c > q0 + row) s[j] = -1e30f;
        }
        // Row max (8 local + across 4-lane group)
        float mt = s[0];
        #pragma unroll
        for (int j = 1; j < 8; j++) mt = fmaxf(mt, s[j]);
        mt = fmaxf(mt, __shfl_xor_sync(0xffffffffu, mt, 1));
        mt = fmaxf(mt, __shfl_xor_sync(0xffffffffu, mt, 2));
        const float m_new = fmaxf(m_run, mt);
        const float alpha = __expf(m_run - m_new);

        float ps = 0.0f;
        #pragma unroll
        for (int j = 0; j < 8; j++) {
            const float p = __expf(s[j] - m_new);
            ps += p;
            p_s[row * 33 + j * 4 + sub] = p;
        }
        ps += __shfl_xor_sync(0xffffffffu, ps, 1);
        ps += __shfl_xor_sync(0xffffffffu, ps, 2);
        l_run = l_run * alpha + ps;
        m_run = m_new;
        #pragma unroll
        for (int d = 0; d < 32; d++) o[d] *= alpha;

        __syncthreads();  // p_s visible to whole block

        // PV: rotate column by row so warp's 8 rows hit distinct bank groups
        #pragma unroll 4
        for (int c = 0; c < BKV; c++) {
            const int cc = (c + row) & (BKV - 1);
            const float p = p_s[row * 33 + cc];
            const float* vrow = &v_s[cc * QPAD + sub * 32];
            #pragma unroll
            for (int k4 = 0; k4 < 8; k4++) {
                float4 vv = *(const float4*)(vrow + k4 * 4);
                o[k4 * 4 + 0] += p * vv.x;
                o[k4 * 4 + 1] += p * vv.y;
                o[k4 * 4 + 2] += p * vv.z;
                o[k4 * 4 + 3] += p * vv.w;
            }
        }
    }

    // Epilogue
    const float inv_l = 1.0f / l_run;
    float* outp = &attn_out[(long)(q0 + row) * HID + h * HD + sub * 32];
    #pragma unroll
    for (int k4 = 0; k4 < 8; k4++) {
        float4 ov;
        ov.x = o[k4 * 4 + 0] * inv_l;
        ov.y = o[k4 * 4 + 1] * inv_l;
        ov.z = o[k4 * 4 + 2] * inv_l;
        ov.w = o[k4 * 4 + 3] * inv_l;
        *(float4*)(outp + k4 * 4) = ov;
    }
}

// ---------------------------------------------------------------------------
extern "C" void kernel_launch(void* const* d_in, const int* in_sizes, int n_in,
                              void* d_out, int out_size)
{
    const float* x    = (const float*)d_in[0];
    const float* wqkv = (const float*)d_in[1];
    const float* bqkv = (const float*)d_in[2];
    const float* wo   = (const float*)d_in[3];
    const float* bo   = (const float*)d_in[4];
    float* out = (float*)d_out;

    float *qkv_buf, *attn_buf;
    cudaGetSymbolAddress((void**)&qkv_buf,  g_qkv);
    cudaGetSymbolAddress((void**)&attn_buf, g_attn);

    // 1) QKV projection: [2048,6400] = x[2048,6144] @ wqkv[6400,6144]^T + bqkv
    {
        dim3 grid(QKV_OUT / 128, S_LEN / 128);
        sgemm_nt_bias<<<grid, 256>>>(x, wqkv, bqkv, qkv_buf, S_LEN, QKV_OUT, HID);
    }

    // 2) MQA causal flash attention -> attn_buf [2048, 6144]
    {
        size_t shmem = (size_t)(BQ * QPAD + 2 * BKV * QPAD + BQ * 33) * sizeof(float);
        cudaFuncSetAttribute(mqa_flash_kernel,
                             cudaFuncAttributeMaxDynamicSharedMemorySize, (int)shmem);
        dim3 grid(S_LEN / BQ, NH);
        mqa_flash_kernel<<<grid, 256, shmem>>>(qkv_buf, attn_buf);
    }

    // 3) Output projection: out[2048,6144] = attn @ wo[6144,6144]^T + bo
    {
        dim3 grid(HID / 128, S_LEN / 128);
        sgemm_nt_bias<<<grid, 256>>>(attn_buf, wo, bo, out, S_LEN, HID, HID);
    }
}

// round 3
// speedup vs baseline: 1.3749x; 1.3749x over previous
#include <cuda_runtime.h>
#include <cstdint>

// Problem constants (B=1 fixed)
#define S_LEN   2048
#define HID     6144
#define QKV_OUT 6400   // HID + 2*128
#define NH      48
#define HD      128

// Scratch (no cudaMalloc allowed)
__device__ float g_qkv [S_LEN * QKV_OUT];
__device__ float g_attn[S_LEN * HID];

__device__ __forceinline__ uint32_t f2tf32(float v) {
    uint32_t u;
    asm("cvt.rna.tf32.f32 %0, %1;" : "=r"(u) : "f"(v));
    return u;
}

__device__ __forceinline__ void mma_tf32(float* d, const uint32_t* a, const uint32_t* b) {
    asm volatile(
        "mma.sync.aligned.m16n8k8.row.col.f32.tf32.tf32.f32 "
        "{%0,%1,%2,%3}, {%4,%5,%6,%7}, {%8,%9}, {%0,%1,%2,%3};"
        : "+f"(d[0]), "+f"(d[1]), "+f"(d[2]), "+f"(d[3])
        : "r"(a[0]), "r"(a[1]), "r"(a[2]), "r"(a[3]), "r"(b[0]), "r"(b[1]));
}

// ---------------------------------------------------------------------------
// tf32 HMMA GEMM: C[M,N] = A[M,K] * B[N,K]^T + bias[N]
// CTA 128x128, BK=32, 256 threads (8 warps, 2 Mrows x 4 Ncols, warp tile 64x32),
// double-buffered smem, rows padded to 36 floats (conflict-free frag LDS).
// M%128==0, N%128==0, K%32==0.
// ---------------------------------------------------------------------------
#define APAD 36
#define SLOT_FLOATS (128 * APAD)            // 4608 floats per tile
#define STAGE_FLOATS (2 * SLOT_FLOATS)      // A + B per stage

__global__ void __launch_bounds__(256) gemm_tf32_hmma(
    const float* __restrict__ A, const float* __restrict__ B,
    const float* __restrict__ bias, float* __restrict__ C,
    int M, int N, int K)
{
    extern __shared__ float sm[];

    const int tid = threadIdx.x;
    const int wid = tid >> 5, lid = tid & 31;
    const int g   = lid >> 2;       // groupID (row within frag)
    const int t4  = lid & 3;        // threadID_in_group
    const int wr  = wid >> 2;       // 0..1: M warp row (64 rows each)
    const int wc  = wid & 3;        // 0..3: N warp col (32 cols each)

    const int bm = blockIdx.y * 128, bn = blockIdx.x * 128;

    // Loader: thread t handles row r = t>>1, 16 consecutive cols at (t&1)*16
    const int lr = tid >> 1;
    const int lc = (tid & 1) * 16;
    const float* Ag = A + (long)(bm + lr) * K + lc;
    const float* Bg = B + (long)(bn + lr) * K + lc;
    const uint32_t s_off = (uint32_t)(lr * APAD + lc);

    float acc[4][4][4];
    #pragma unroll
    for (int i = 0; i < 4; i++)
        #pragma unroll
        for (int j = 0; j < 4; j++)
            #pragma unroll
            for (int k = 0; k < 4; k++) acc[i][j][k] = 0.0f;

    const int NS = K >> 5;

    float4 ar[4], br[4];

    // prologue: LDG stage 0, STS to slot 0
    #pragma unroll
    for (int i = 0; i < 4; i++) {
        ar[i] = *(const float4*)(Ag + i * 4);
        br[i] = *(const float4*)(Bg + i * 4);
    }
    {
        uint32_t* As = (uint32_t*)sm;
        uint32_t* Bs = As + SLOT_FLOATS;
        #pragma unroll
        for (int i = 0; i < 4; i++) {
            uint32_t o = s_off + i * 4;
            As[o+0]=f2tf32(ar[i].x); As[o+1]=f2tf32(ar[i].y);
            As[o+2]=f2tf32(ar[i].z); As[o+3]=f2tf32(ar[i].w);
            Bs[o+0]=f2tf32(br[i].x); Bs[o+1]=f2tf32(br[i].y);
            Bs[o+2]=f2tf32(br[i].z); Bs[o+3]=f2tf32(br[i].w);
        }
    }
    __syncthreads();

    for (int s = 0; s < NS; s++) {
        // prefetch next stage into registers (overlaps compute below)
        if (s + 1 < NS) {
            const long koff = 32L * (s + 1);
            #pragma unroll
            for (int i = 0; i < 4; i++) {
                ar[i] = *(const float4*)(Ag + koff + i * 4);
                br[i] = *(const float4*)(Bg + koff + i * 4);
            }
        }

        // compute stage s from slot s&1
        {
            const uint32_t* As = (const uint32_t*)sm + (s & 1) * STAGE_FLOATS;
            const uint32_t* Bs = As + SLOT_FLOATS;
            #pragma unroll
            for (int ks = 0; ks < 4; ks++) {
                const int kk = ks * 8 + t4;
                uint32_t af[4][4], bf[4][2];
                #pragma unroll
                for (int mt = 0; mt < 4; mt++) {
                    const int ra = (wr * 64 + mt * 16 + g) * APAD + kk;
                    af[mt][0] = As[ra];
                    af[mt][1] = As[ra + 8 * APAD];
                    af[mt][2] = As[ra + 4];
                    af[mt][3] = As[ra + 8 * APAD + 4];
                }
                #pragma unroll
                for (int nt = 0; nt < 4; nt++) {
                    const int rb = (wc * 32 + nt * 8 + g) * APAD + kk;
                    bf[nt][0] = Bs[rb];
                    bf[nt][1] = Bs[rb + 4];
                }
                #pragma unroll
                for (int mt = 0; mt < 4; mt++)
                    #pragma unroll
                    for (int nt = 0; nt < 4; nt++)
                        mma_tf32(acc[mt][nt], af[mt], bf[nt]);
            }
        }

        if (s + 1 < NS) {
            __syncthreads();   // all warps done with slot (s+1)&1 (stage s-1)
            uint32_t* As = (uint32_t*)sm + ((s + 1) & 1) * STAGE_FLOATS;
            uint32_t* Bs = As + SLOT_FLOATS;
            #pragma unroll
            for (int i = 0; i < 4; i++) {
                uint32_t o = s_off + i * 4;
                As[o+0]=f2tf32(ar[i].x); As[o+1]=f2tf32(ar[i].y);
                As[o+2]=f2tf32(ar[i].z); As[o+3]=f2tf32(ar[i].w);
                Bs[o+0]=f2tf32(br[i].x); Bs[o+1]=f2tf32(br[i].y);
                Bs[o+2]=f2tf32(br[i].z); Bs[o+3]=f2tf32(br[i].w);
            }
            __syncthreads();
        }
    }

    // Epilogue: c0/c1 at (row, col..col+1), c2/c3 at (row+8, ...)
    #pragma unroll
    for (int mt = 0; mt < 4; mt++) {
        const int row = bm + wr * 64 + mt * 16 + g;
        #pragma unroll
        for (int nt = 0; nt < 4; nt++) {
            const int col = bn + wc * 32 + nt * 8 + t4 * 2;
            const float b0 = bias[col], b1 = bias[col + 1];
            float2 lo, hi;
            lo.x = acc[mt][nt][0] + b0; lo.y = acc[mt][nt][1] + b1;
            hi.x = acc[mt][nt][2] + b0; hi.y = acc[mt][nt][3] + b1;
            *(float2*)&C[(long)row * N + col]       = lo;
            *(float2*)&C[(long)(row + 8) * N + col] = hi;
        }
    }
}

// ---------------------------------------------------------------------------
// MQA causal flash attention (unchanged from R1)
// ---------------------------------------------------------------------------
#define BQ  64
#define BKV 32
#define QPAD 132

__global__ void __launch_bounds__(256, 2) mqa_flash_kernel(
    const float* __restrict__ qkv, float* __restrict__ attn_out)
{
    extern __shared__ float smf[];
    float* q_s = smf;
    float* k_s = q_s + BQ * QPAD;
    float* v_s = k_s + BKV * QPAD;
    float* p_s = v_s + BKV * QPAD;

    const int h   = blockIdx.y;
    const int q0  = blockIdx.x * BQ;
    const int tid = threadIdx.x;
    const int row = tid >> 2;
    const int sub = tid & 3;

    const float scale = 0.08838834764831845f;

    for (int i = tid; i < BQ * HD / 4; i += 256) {
        int r = i >> 5;
        int c = (i & 31) * 4;
        float4 v4 = *(const float4*)&qkv[(long)(q0 + r) * QKV_OUT + h * HD + c];
        v4.x *= scale; v4.y *= scale; v4.z *= scale; v4.w *= scale;
        *(float4*)&q_s[r * QPAD + c] = v4;
    }

    float o[32];
    #pragma unroll
    for (int d = 0; d < 32; d++) o[d] = 0.0f;
    float m_run = -1e30f, l_run = 0.0f;

    const int kt_end = (q0 + BQ - 1) / BKV;
    for (int kt = 0; kt <= kt_end; kt++) {
        const int k0 = kt * BKV;
        __syncthreads();
        for (int i = tid; i < BKV * HD / 4; i += 256) {
            int r = i >> 5;
            int c = (i & 31) * 4;
            long base = (long)(k0 + r) * QKV_OUT;
            *(float4*)&k_s[r * QPAD + c] = *(const float4*)&qkv[base + HID + c];
            *(float4*)&v_s[r * QPAD + c] = *(const float4*)&qkv[base + HID + HD + c];
        }
        __syncthreads();

        float s[8];
        #pragma unroll
        for (int j = 0; j < 8; j++) s[j] = 0.0f;
        const float* qrow = &q_s[row * QPAD];
        #pragma unroll 8
        for (int d4 = 0; d4 < HD; d4 += 4) {
            float4 qv = *(const float4*)(qrow + d4);
            #pragma unroll
            for (int j = 0; j < 8; j++) {
                const int c = j * 4 + sub;
                float4 kv = *(const float4*)&k_s[c * QPAD + d4];
                s[j] += qv.x * kv.x + qv.y * kv.y + qv.z * kv.z + qv.w * kv.w;
            }
        }
        #pragma unroll
        for (int j = 0; j < 8; j++) {
            const int c = j * 4 + sub;
            if (k0 + c > q0 + row) s[j] = -1e30f;
        }
        float mt = s[0];
        #pragma unroll
        for (int j = 1; j < 8; j++) mt = fmaxf(mt, s[j]);
        mt = fmaxf(mt, __shfl_xor_sync(0xffffffffu, mt, 1));
        mt = fmaxf(mt, __shfl_xor_sync(0xffffffffu, mt, 2));
        const float m_new = fmaxf(m_run, mt);
        const float alpha = __expf(m_run - m_new);

        float ps = 0.0f;
        #pragma unroll
        for (int j = 0; j < 8; j++) {
            const float p = __expf(s[j] - m_new);
            ps += p;
            p_s[row * 33 + j * 4 + sub] = p;
        }
        ps += __shfl_xor_sync(0xffffffffu, ps, 1);
        ps += __shfl_xor_sync(0xffffffffu, ps, 2);
        l_run = l_run * alpha + ps;
        m_run = m_new;
        #pragma unroll
        for (int d = 0; d < 32; d++) o[d] *= alpha;

        __syncthreads();

        #pragma unroll 4
        for (int c = 0; c < BKV; c++) {
            const int cc = (c + row) & (BKV - 1);
            const float p = p_s[row * 33 + cc];
            const float* vrow = &v_s[cc * QPAD + sub * 32];
            #pragma unroll
            for (int k4 = 0; k4 < 8; k4++) {
                float4 vv = *(const float4*)(vrow + k4 * 4);
                o[k4 * 4 + 0] += p * vv.x;
                o[k4 * 4 + 1] += p * vv.y;
                o[k4 * 4 + 2] += p * vv.z;
                o[k4 * 4 + 3] += p * vv.w;
            }
        }
    }

    const float inv_l = 1.0f / l_run;
    float* outp = &attn_out[(long)(q0 + row) * HID + h * HD + sub * 32];
    #pragma unroll
    for (int k4 = 0; k4 < 8; k4++) {
        float4 ov;
        ov.x = o[k4 * 4 + 0] * inv_l;
        ov.y = o[k4 * 4 + 1] * inv_l;
        ov.z = o[k4 * 4 + 2] * inv_l;
        ov.w = o[k4 * 4 + 3] * inv_l;
        *(float4*)(outp + k4 * 4) = ov;
    }
}

// ---------------------------------------------------------------------------
extern "C" void kernel_launch(void* const* d_in, const int* in_sizes, int n_in,
                              void* d_out, int out_size)
{
    const float* x    = (const float*)d_in[0];
    const float* wqkv = (const float*)d_in[1];
    const float* bqkv = (const float*)d_in[2];
    const float* wo   = (const float*)d_in[3];
    const float* bo   = (const float*)d_in[4];
    float* out = (float*)d_out;

    float *qkv_buf, *attn_buf;
    cudaGetSymbolAddress((void**)&qkv_buf,  g_qkv);
    cudaGetSymbolAddress((void**)&attn_buf, g_attn);

    const int gemm_smem = 2 * STAGE_FLOATS * sizeof(float);  // 73728
    cudaFuncSetAttribute(gemm_tf32_hmma,
                         cudaFuncAttributeMaxDynamicSharedMemorySize, gemm_smem);

    // 1) QKV projection: [2048,6400] = x @ wqkv^T + bqkv
    {
        dim3 grid(QKV_OUT / 128, S_LEN / 128);
        gemm_tf32_hmma<<<grid, 256, gemm_smem>>>(x, wqkv, bqkv, qkv_buf,
                                                 S_LEN, QKV_OUT, HID);
    }

    // 2) MQA causal flash attention -> attn_buf [2048, 6144]
    {
        size_t shmem = (size_t)(BQ * QPAD + 2 * BKV * QPAD + BQ * 33) * sizeof(float);
        cudaFuncSetAttribute(mqa_flash_kernel,
                             cudaFuncAttributeMaxDynamicSharedMemorySize, (int)shmem);
        dim3 grid(S_LEN / BQ, NH);
        mqa_flash_kernel<<<grid, 256, shmem>>>(qkv_buf, attn_buf);
    }

    // 3) Output projection: out[2048,6144] = attn @ wo^T + bo
    {
        dim3 grid(HID / 128, S_LEN / 128);
        gemm_tf32_hmma<<<grid, 256, gemm_smem>>>(attn_buf, wo, bo, out,
                                                 S_LEN, HID, HID);
    }
}

// round 5
// speedup vs baseline: 3.8203x; 2.7786x over previous
#include <cuda_runtime.h>
#include <cuda_bf16.h>
#include <cstdint>

// Problem constants (B=1 fixed)
#define S_LEN   2048
#define HID     6144
#define QKV_OUT 6400   // HID + 2*128
#define NH      48
#define HD      128

// Scratch (no cudaMalloc allowed)
__device__ float g_qkv [S_LEN * QKV_OUT];
__device__ float g_attn[S_LEN * HID];

// ---------------------------------------------------------------------------
// helpers
// ---------------------------------------------------------------------------
__device__ __forceinline__ uint32_t smem_u32(const void* p) {
    uint32_t a;
    asm("{ .reg .u64 t; cvta.to.shared.u64 t, %1; cvt.u32.u64 %0, t; }"
        : "=r"(a) : "l"(p));
    return a;
}

__device__ __forceinline__ void mma_bf16(float* d, const uint32_t* a, const uint32_t* b) {
    asm volatile(
        "mma.sync.aligned.m16n8k16.row.col.f32.bf16.bf16.f32 "
        "{%0,%1,%2,%3}, {%4,%5,%6,%7}, {%8,%9}, {%0,%1,%2,%3};"
        : "+f"(d[0]), "+f"(d[1]), "+f"(d[2]), "+f"(d[3])
        : "r"(a[0]), "r"(a[1]), "r"(a[2]), "r"(a[3]), "r"(b[0]), "r"(b[1]));
}

__device__ __forceinline__ void ldsm_x2_t(uint32_t& r0, uint32_t& r1, uint32_t addr) {
    asm volatile("ldmatrix.sync.aligned.m8n8.x2.trans.shared.b16 {%0,%1}, [%2];"
                 : "=r"(r0), "=r"(r1) : "r"(addr));
}

// split two floats into bf16 hi pair + bf16 lo (residual) pair
__device__ __forceinline__ void pack_split2(float x, float y, uint32_t& hi, uint32_t& lo) {
    __nv_bfloat162 h = __floats2bfloat162_rn(x, y);
    float2 hf = __bfloat1622float2(h);
    __nv_bfloat162 l = __floats2bfloat162_rn(x - hf.x, y - hf.y);
    hi = *reinterpret_cast<uint32_t*>(&h);
    lo = *reinterpret_cast<uint32_t*>(&l);
}

// load 16 consecutive floats, split, store 8 hi u32 at hi[], 8 lo u32 at lo[]
__device__ __forceinline__ void split16(const float* src, uint32_t* hi, uint32_t* lo,
                                        float scale) {
    #pragma unroll
    for (int i = 0; i < 4; i++) {
        float4 f = *(const float4*)(src + i * 4);
        f.x *= scale; f.y *= scale; f.z *= scale; f.w *= scale;
        uint32_t h0, l0, h1, l1;
        pack_split2(f.x, f.y, h0, l0);
        pack_split2(f.z, f.w, h1, l1);
        hi[i * 2] = h0; hi[i * 2 + 1] = h1;
        lo[i * 2] = l0; lo[i * 2 + 1] = l1;
    }
}

// ---------------------------------------------------------------------------
// bf16-split GEMM: C[M,N] = A[M,K] * B[N,K]^T + bias[N]
// CTA 128x128, BK=32, 256 threads, warp tile 64x32, 3-term bf16 decomposition,
// double-buffered smem (pitch 36 u32: 16 hi pairs | 16 lo pairs | 4 pad).
// ---------------------------------------------------------------------------
#define GP 36
#define GSLOT  (128 * GP)
#define GSTAGE (2 * GSLOT)

__global__ void __launch_bounds__(256) gemm_bf16s(
    const float* __restrict__ A, const float* __restrict__ B,
    const float* __restrict__ bias, float* __restrict__ C,
    int M, int N, int K)
{
    extern __shared__ uint32_t gsm[];

    const int tid = threadIdx.x;
    const int wid = tid >> 5, lid = tid & 31;
    const int g   = lid >> 2;
    const int t4  = lid & 3;
    const int wr  = wid >> 2;       // 0..1
    const int wc  = wid & 3;        // 0..3

    const int bm = blockIdx.y * 128, bn = blockIdx.x * 128;

    const int lr = tid >> 1;        // 0..127
    const int pb = (tid & 1) * 8;   // pair base 0 or 8
    const float* Ag = A + (long)(bm + lr) * K + pb * 2;
    const float* Bg = B + (long)(bn + lr) * K + pb * 2;

    float acc[4][4][4];
    #pragma unroll
    for (int i = 0; i < 4; i++)
        #pragma unroll
        for (int j = 0; j < 4; j++)
            #pragma unroll
            for (int k = 0; k < 4; k++) acc[i][j][k] = 0.0f;

    const int NS = K >> 5;
    float4 ar[4], br[4];

    // prologue
    #pragma unroll
    for (int i = 0; i < 4; i++) {
        ar[i] = *(const float4*)(Ag + i * 4);
        br[i] = *(const float4*)(Bg + i * 4);
    }
    {
        uint32_t* As = gsm;
        uint32_t* Bs = As + GSLOT;
        const uint32_t o = (uint32_t)(lr * GP + pb);
        split16((const float*)ar, As + o, As + o + 16, 1.0f);
        split16((const float*)br, Bs + o, Bs + o + 16, 1.0f);
    }
    __syncthreads();

    for (int s = 0; s < NS; s++) {
        if (s + 1 < NS) {
            const long koff = 32L * (s + 1);
            #pragma unroll
            for (int i = 0; i < 4; i++) {
                ar[i] = *(const float4*)(Ag + koff + i * 4);
                br[i] = *(const float4*)(Bg + koff + i * 4);
            }
        }

        // compute on slot s&1
        {
            const uint32_t* As = gsm + (s & 1) * GSTAGE;
            const uint32_t* Bs = As + GSLOT;
            #pragma unroll
            for (int ks = 0; ks < 2; ks++) {
                uint32_t ah[4][4], al[4][4];
                #pragma unroll
                for (int mt = 0; mt < 4; mt++) {
                    const int ro = (wr * 64 + mt * 16 + g) * GP + ks * 8 + t4;
                    ah[mt][0] = As[ro];          ah[mt][1] = As[ro + 8 * GP];
                    ah[mt][2] = As[ro + 4];      ah[mt][3] = As[ro + 8 * GP + 4];
                    al[mt][0] = As[ro + 16];     al[mt][1] = As[ro + 8 * GP + 16];
                    al[mt][2] = As[ro + 20];     al[mt][3] = As[ro + 8 * GP + 20];
                }
                #pragma unroll
                for (int nt = 0; nt < 4; nt++) {
                    const int rb = (wc * 32 + nt * 8 + g) * GP + ks * 8 + t4;
                    uint32_t bh[2] = { Bs[rb],      Bs[rb + 4]  };
                    uint32_t bl[2] = { Bs[rb + 16], Bs[rb + 20] };
                    #pragma unroll
                    for (int mt = 0; mt < 4; mt++) {
                        mma_bf16(acc[mt][nt], ah[mt], bh);
                        mma_bf16(acc[mt][nt], ah[mt], bl);
                        mma_bf16(acc[mt][nt], al[mt], bh);
                    }
                }
            }
        }

        if (s + 1 < NS) {
            uint32_t* As = gsm + ((s + 1) & 1) * GSTAGE;
            uint32_t* Bs = As + GSLOT;
            const uint32_t o = (uint32_t)(lr * GP + pb);
            split16((const float*)ar, As + o, As + o + 16, 1.0f);
            split16((const float*)br, Bs + o, Bs + o + 16, 1.0f);
            __syncthreads();
        }
    }

    // epilogue: c0,c1 -> (row g, col 2t4..), c2,c3 -> (row g+8)
    #pragma unroll
    for (int mt = 0; mt < 4; mt++) {
        const int row = bm + wr * 64 + mt * 16 + g;
        #pragma unroll
        for (int nt = 0; nt < 4; nt++) {
            const int col = bn + wc * 32 + nt * 8 + t4 * 2;
            const float b0 = bias[col], b1 = bias[col + 1];
            float2 lo, hi;
            lo.x = acc[mt][nt][0] + b0; lo.y = acc[mt][nt][1] + b1;
            hi.x = acc[mt][nt][2] + b0; hi.y = acc[mt][nt][3] + b1;
            *(float2*)&C[(long)row * N + col]       = lo;
            *(float2*)&C[(long)(row + 8) * N + col] = hi;
        }
    }
}

// ---------------------------------------------------------------------------
// MQA causal flash attention, bf16-split HMMA.
// CTA: 128 threads (4 warps x m16), BQ=64, BKV=64, D=128.
// smem pitch 132 u32 per row: 64 hi pairs | 64 lo pairs | 4 pad.
// Loaders: 2 threads per row, each covering 4 chunks of 16 floats (full D=128).
// ---------------------------------------------------------------------------
#define QP 132

__global__ void __launch_bounds__(128) mqa_flash_hmma(
    const float* __restrict__ qkv, float* __restrict__ attn_out)
{
    extern __shared__ uint32_t asm_[];
    uint32_t* q_s = asm_;                 // [64][QP]
    uint32_t* k_s = q_s + 64 * QP;
    uint32_t* v_s = k_s + 64 * QP;

    const int h  = blockIdx.y;
    const int bq = blockIdx.x;
    const int q0 = bq * 64;
    const int tid = threadIdx.x;
    const int wid = tid >> 5, lid = tid & 31;
    const int g = lid >> 2, t4 = lid & 3;

    const uint32_t v_base = smem_u32(v_s);

    const int lr  = tid >> 1;            // row 0..63
    const int lc0 = (tid & 1) * 16;      // chunk base 0 or 16

    // Load Q tile (pre-scaled by 1/sqrt(128)), split into hi/lo bf16.
    {
        const float* src = qkv + (long)(q0 + lr) * QKV_OUT + h * HD;
        uint32_t* dst = q_s + lr * QP;
        #pragma unroll
        for (int jj = 0; jj < 4; jj++) {
            const int c16 = lc0 + 32 * jj;   // covers d = 0..127
            split16(src + c16, dst + (c16 >> 1), dst + (c16 >> 1) + 64,
                    0.08838834764831845f);
        }
    }

    float o[16][4];
    #pragma unroll
    for (int i = 0; i < 16; i++)
        #pragma unroll
        for (int j = 0; j < 4; j++) o[i][j] = 0.0f;
    float m0 = -1e30f, m1 = -1e30f, l0 = 0.0f, l1 = 0.0f;

    const int row0 = q0 + wid * 16 + g;
    const int row1 = row0 + 8;

    for (int kt = 0; kt <= bq; kt++) {
        __syncthreads();   // Q ready / previous-iter smem reads done
        {
            const float* kp = qkv + (long)(kt * 64 + lr) * QKV_OUT + HID;
            uint32_t* kd = k_s + lr * QP;
            uint32_t* vd = v_s + lr * QP;
            #pragma unroll
            for (int jj = 0; jj < 4; jj++) {
                const int c16 = lc0 + 32 * jj;
                split16(kp + c16,      kd + (c16 >> 1), kd + (c16 >> 1) + 64, 1.0f);
                split16(kp + HD + c16, vd + (c16 >> 1), vd + (c16 >> 1) + 64, 1.0f);
            }
        }
        __syncthreads();

        // ---- S = Q K^T (3-term bf16) ----
        float s[8][4];
        #pragma unroll
        for (int nt = 0; nt < 8; nt++)
            #pragma unroll
            for (int j = 0; j < 4; j++) s[nt][j] = 0.0f;

        const uint32_t* qb = q_s + (wid * 16) * QP;
        #pragma unroll
        for (int ks = 0; ks < 8; ks++) {
            uint32_t ah[4], al[4];
            const int ro = g * QP + ks * 8 + t4;
            ah[0] = qb[ro];          ah[1] = qb[ro + 8 * QP];
            ah[2] = qb[ro + 4];      ah[3] = qb[ro + 8 * QP + 4];
            al[0] = qb[ro + 64];     al[1] = qb[ro + 8 * QP + 64];
            al[2] = qb[ro + 68];     al[3] = qb[ro + 8 * QP + 68];
            #pragma unroll
            for (int nt = 0; nt < 8; nt++) {
                const int rb = (nt * 8 + g) * QP + ks * 8 + t4;
                uint32_t bh[2] = { k_s[rb],      k_s[rb + 4]  };
                uint32_t bl[2] = { k_s[rb + 64], k_s[rb + 68] };
                mma_bf16(s[nt], ah, bh);
                mma_bf16(s[nt], ah, bl);
                mma_bf16(s[nt], al, bh);
            }
        }

        // causal mask (diagonal tile only)
        if (kt == bq) {
            #pragma unroll
            for (int nt = 0; nt < 8; nt++) {
                const int col = kt * 64 + nt * 8 + 2 * t4;
                if (col     > row0) s[nt][0] = -1e30f;
                if (col + 1 > row0) s[nt][1] = -1e30f;
                if (col     > row1) s[nt][2] = -1e30f;
                if (col + 1 > row1) s[nt][3] = -1e30f;
            }
        }

        // ---- online softmax (rows g and g+8) ----
        float mt0 = -1e30f, mt1 = -1e30f;
        #pragma unroll
        for (int nt = 0; nt < 8; nt++) {
            mt0 = fmaxf(mt0, fmaxf(s[nt][0], s[nt][1]));
            mt1 = fmaxf(mt1, fmaxf(s[nt][2], s[nt][3]));
        }
        mt0 = fmaxf(mt0, __shfl_xor_sync(0xffffffffu, mt0, 1));
        mt0 = fmaxf(mt0, __shfl_xor_sync(0xffffffffu, mt0, 2));
        mt1 = fmaxf(mt1, __shfl_xor_sync(0xffffffffu, mt1, 1));
        mt1 = fmaxf(mt1, __shfl_xor_sync(0xffffffffu, mt1, 2));

        const float mn0 = fmaxf(m0, mt0), mn1 = fmaxf(m1, mt1);
        const float al0 = __expf(m0 - mn0), al1 = __expf(m1 - mn1);

        float ps0 = 0.0f, ps1 = 0.0f;
        #pragma unroll
        for (int nt = 0; nt < 8; nt++) {
            s[nt][0] = __expf(s[nt][0] - mn0);
            s[nt][1] = __expf(s[nt][1] - mn0);
            s[nt][2] = __expf(s[nt][2] - mn1);
            s[nt][3] = __expf(s[nt][3] - mn1);
            ps0 += s[nt][0] + s[nt][1];
            ps1 += s[nt][2] + s[nt][3];
        }
        ps0 += __shfl_xor_sync(0xffffffffu, ps0, 1);
        ps0 += __shfl_xor_sync(0xffffffffu, ps0, 2);
        ps1 += __shfl_xor_sync(0xffffffffu, ps1, 1);
        ps1 += __shfl_xor_sync(0xffffffffu, ps1, 2);
        l0 = l0 * al0 + ps0; m0 = mn0;
        l1 = l1 * al1 + ps1; m1 = mn1;

        #pragma unroll
        for (int nt = 0; nt < 16; nt++) {
            o[nt][0] *= al0; o[nt][1] *= al0;
            o[nt][2] *= al1; o[nt][3] *= al1;
        }

        // ---- O += P V (3-term bf16); P frags packed directly from S frags ----
        #pragma unroll
        for (int jj = 0; jj < 4; jj++) {
            uint32_t ph[4], pl[4];
            pack_split2(s[2*jj][0],   s[2*jj][1],   ph[0], pl[0]);
            pack_split2(s[2*jj][2],   s[2*jj][3],   ph[1], pl[1]);
            pack_split2(s[2*jj+1][0], s[2*jj+1][1], ph[2], pl[2]);
            pack_split2(s[2*jj+1][2], s[2*jj+1][3], ph[3], pl[3]);

            const uint32_t rowaddr = v_base + (uint32_t)(((jj * 16 + (lid & 15)) * QP) * 4);
            #pragma unroll
            for (int nt = 0; nt < 16; nt++) {
                uint32_t bh[2], bl[2];
                ldsm_x2_t(bh[0], bh[1], rowaddr + nt * 16);
                ldsm_x2_t(bl[0], bl[1], rowaddr + 256 + nt * 16);
                mma_bf16(o[nt], ph, bh);
                mma_bf16(o[nt], ph, bl);
                mma_bf16(o[nt], pl, bh);
            }
        }
    }

    // epilogue
    const float i0 = 1.0f / l0, i1 = 1.0f / l1;
    #pragma unroll
    for (int nt = 0; nt < 16; nt++) {
        const int d = nt * 8 + 2 * t4;
        float2 a, b;
        a.x = o[nt][0] * i0; a.y = o[nt][1] * i0;
        b.x = o[nt][2] * i1; b.y = o[nt][3] * i1;
        *(float2*)&attn_out[(long)row0 * HID + h * HD + d] = a;
        *(float2*)&attn_out[(long)row1 * HID + h * HD + d] = b;
    }
}

// ---------------------------------------------------------------------------
extern "C" void kernel_launch(void* const* d_in, const int* in_sizes, int n_in,
                              void* d_out, int out_size)
{
    const float* x    = (const float*)d_in[0];
    const float* wqkv = (const float*)d_in[1];
    const float* bqkv = (const float*)d_in[2];
    const float* wo   = (const float*)d_in[3];
    const float* bo   = (const float*)d_in[4];
    float* out = (float*)d_out;

    float *qkv_buf, *attn_buf;
    cudaGetSymbolAddress((void**)&qkv_buf,  g_qkv);
    cudaGetSymbolAddress((void**)&attn_buf, g_attn);

    const int gemm_smem = 2 * GSTAGE * sizeof(uint32_t);   // 73728
    cudaFuncSetAttribute(gemm_bf16s,
                         cudaFuncAttributeMaxDynamicSharedMemorySize, gemm_smem);

    const int attn_smem = 3 * 64 * QP * sizeof(uint32_t);  // 101376
    cudaFuncSetAttribute(mqa_flash_hmma,
                         cudaFuncAttributeMaxDynamicSharedMemorySize, attn_smem);

    // 1) QKV projection
    {
        dim3 grid(QKV_OUT / 128, S_LEN / 128);
        gemm_bf16s<<<grid, 256, gemm_smem>>>(x, wqkv, bqkv, qkv_buf,
                                             S_LEN, QKV_OUT, HID);
    }
    // 2) attention
    {
        dim3 grid(S_LEN / 64, NH);
        mqa_flash_hmma<<<grid, 128, attn_smem>>>(qkv_buf, attn_buf);
    }
    // 3) output projection
    {
        dim3 grid(HID / 128, S_LEN / 128);
        gemm_bf16s<<<grid, 256, gemm_smem>>>(attn_buf, wo, bo, out,
                                             S_LEN, HID, HID);
    }
}

// round 6
// speedup vs baseline: 4.4309x; 1.1598x over previous
#include <cuda_runtime.h>
#include <cuda_bf16.h>
#include <cstdint>

// Problem constants (B=1 fixed)
#define S_LEN   2048
#define HID     6144
#define QKV_OUT 6400   // HID + 2*128
#define NH      48
#define HD      128

// Scratch (no cudaMalloc allowed)
__device__ float g_qkv [S_LEN * QKV_OUT];
__device__ float g_attn[S_LEN * HID];

// ---------------------------------------------------------------------------
// helpers
// ---------------------------------------------------------------------------
__device__ __forceinline__ uint32_t smem_u32(const void* p) {
    uint32_t a;
    asm("{ .reg .u64 t; cvta.to.shared.u64 t, %1; cvt.u32.u64 %0, t; }"
        : "=r"(a) : "l"(p));
    return a;
}

__device__ __forceinline__ void mma_bf16(float* d, const uint32_t* a, const uint32_t* b) {
    asm volatile(
        "mma.sync.aligned.m16n8k16.row.col.f32.bf16.bf16.f32 "
        "{%0,%1,%2,%3}, {%4,%5,%6,%7}, {%8,%9}, {%0,%1,%2,%3};"
        : "+f"(d[0]), "+f"(d[1]), "+f"(d[2]), "+f"(d[3])
        : "r"(a[0]), "r"(a[1]), "r"(a[2]), "r"(a[3]), "r"(b[0]), "r"(b[1]));
}

__device__ __forceinline__ void ldsm_x4(uint32_t* r, uint32_t addr) {
    asm volatile("ldmatrix.sync.aligned.m8n8.x4.shared.b16 {%0,%1,%2,%3}, [%4];"
                 : "=r"(r[0]), "=r"(r[1]), "=r"(r[2]), "=r"(r[3]) : "r"(addr));
}
__device__ __forceinline__ void ldsm_x2(uint32_t* r, uint32_t addr) {
    asm volatile("ldmatrix.sync.aligned.m8n8.x2.shared.b16 {%0,%1}, [%2];"
                 : "=r"(r[0]), "=r"(r[1]) : "r"(addr));
}
__device__ __forceinline__ void ldsm_x2_t(uint32_t& r0, uint32_t& r1, uint32_t addr) {
    asm volatile("ldmatrix.sync.aligned.m8n8.x2.trans.shared.b16 {%0,%1}, [%2];"
                 : "=r"(r0), "=r"(r1) : "r"(addr));
}

// split two floats into bf16 hi pair + bf16 lo (residual) pair
__device__ __forceinline__ void pack_split2(float x, float y, uint32_t& hi, uint32_t& lo) {
    __nv_bfloat162 h = __floats2bfloat162_rn(x, y);
    float2 hf = __bfloat1622float2(h);
    __nv_bfloat162 l = __floats2bfloat162_rn(x - hf.x, y - hf.y);
    hi = *reinterpret_cast<uint32_t*>(&h);
    lo = *reinterpret_cast<uint32_t*>(&l);
}

// split 8 floats (two float4) -> 4 hi u32 + 4 lo u32
__device__ __forceinline__ void split8(const float4& f0, const float4& f1,
                                       uint32_t* hi, uint32_t* lo) {
    pack_split2(f0.x, f0.y, hi[0], lo[0]);
    pack_split2(f0.z, f0.w, hi[1], lo[1]);
    pack_split2(f1.x, f1.y, hi[2], lo[2]);
    pack_split2(f1.z, f1.w, hi[3], lo[3]);
}

// load 16 consecutive floats, split, store 8 hi u32 at hi[], 8 lo u32 at lo[]
__device__ __forceinline__ void split16(const float* src, uint32_t* hi, uint32_t* lo,
                                        float scale) {
    #pragma unroll
    for (int i = 0; i < 4; i++) {
        float4 f = *(const float4*)(src + i * 4);
        f.x *= scale; f.y *= scale; f.z *= scale; f.w *= scale;
        uint32_t h0, l0, h1, l1;
        pack_split2(f.x, f.y, h0, l0);
        pack_split2(f.z, f.w, h1, l1);
        hi[i * 2] = h0; hi[i * 2 + 1] = h1;
        lo[i * 2] = l0; lo[i * 2 + 1] = l1;
    }
}

// ---------------------------------------------------------------------------
// bf16-split GEMM: C[M,N] = A[M,K] * B[N,K]^T + bias[N]
// CTA 128x128, BK=16, 256 threads, warp tile 64x32, 3-term bf16 decomposition.
// Row pitch 20 u32 (80B): 8 hi u32 | 8 lo u32 | 4 pad -> 5-group stagger makes
// every 8-row ldmatrix phase conflict-free. 2 CTAs/SM via launch_bounds.
// ---------------------------------------------------------------------------
#define GP2   20
#define GTILE (128 * GP2)      // 2560 u32 per tile
#define GSTG  (2 * GTILE)      // A + B per stage

__global__ void __launch_bounds__(256, 2) gemm_bf16s(
    const float* __restrict__ A, const float* __restrict__ B,
    const float* __restrict__ bias, float* __restrict__ C,
    int M, int N, int K)
{
    extern __shared__ uint32_t gsm[];
    const uint32_t smb = smem_u32(gsm);

    const int tid = threadIdx.x;
    const int wid = tid >> 5, lid = tid & 31;
    const int g   = lid >> 2;
    const int t4  = lid & 3;
    const int wr  = wid >> 2;       // 0..1
    const int wc  = wid & 3;        // 0..3

    const int bm = blockIdx.y * 128, bn = blockIdx.x * 128;

    // loaders: 2 threads per row, each 8 consecutive floats
    const int lr   = tid >> 1;
    const int half = tid & 1;
    const float* Ag = A + (long)(bm + lr) * K + half * 8;
    const float* Bg = B + (long)(bn + lr) * K + half * 8;
    const uint32_t sto = (uint32_t)(lr * GP2 + half * 4);   // hi chunk u32 offset

    // ldmatrix lane addresses (u32 offsets within a tile)
    const uint32_t a_row = (uint32_t)((wr * 64 + (lid & 15)) * GP2 + (lid >> 4) * 4);
    const uint32_t b_row = (uint32_t)((wc * 32 + (lid & 7)) * GP2 + ((lid >> 3) & 1) * 4);

    float acc[4][4][4];
    #pragma unroll
    for (int i = 0; i < 4; i++)
        #pragma unroll
        for (int j = 0; j < 4; j++)
            #pragma unroll
            for (int k = 0; k < 4; k++) acc[i][j][k] = 0.0f;

    const int NS = K >> 4;
    float4 ar0, ar1, br0, br1;

    // prologue: stage 0
    ar0 = *(const float4*)(Ag);     ar1 = *(const float4*)(Ag + 4);
    br0 = *(const float4*)(Bg);     br1 = *(const float4*)(Bg + 4);
    {
        uint32_t hi[4], lo[4];
        split8(ar0, ar1, hi, lo);
        *(uint4*)(gsm + sto)     = *(uint4*)hi;
        *(uint4*)(gsm + sto + 8) = *(uint4*)lo;
        split8(br0, br1, hi, lo);
        *(uint4*)(gsm + GTILE + sto)     = *(uint4*)hi;
        *(uint4*)(gsm + GTILE + sto + 8) = *(uint4*)lo;
    }
    __syncthreads();

    for (int s = 0; s < NS; s++) {
        if (s + 1 < NS) {
            const long koff = 16L * (s + 1);
            ar0 = *(const float4*)(Ag + koff);  ar1 = *(const float4*)(Ag + koff + 4);
            br0 = *(const float4*)(Bg + koff);  br1 = *(const float4*)(Bg + koff + 4);
        }

        // compute on slot s&1
        {
            const uint32_t abase = smb + ((s & 1) * GSTG + a_row) * 4u;
            const uint32_t bbase = smb + ((s & 1) * GSTG + GTILE + b_row) * 4u;

            uint32_t ah[4][4], al[4][4];
            #pragma unroll
            for (int mt = 0; mt < 4; mt++) {
                ldsm_x4(ah[mt], abase + mt * (16 * GP2 * 4));
                ldsm_x4(al[mt], abase + mt * (16 * GP2 * 4) + 32);
            }
            #pragma unroll
            for (int nt = 0; nt < 4; nt++) {
                uint32_t bh[2], bl[2];
                ldsm_x2(bh, bbase + nt * (8 * GP2 * 4));
                ldsm_x2(bl, bbase + nt * (8 * GP2 * 4) + 32);
                #pragma unroll
                for (int mt = 0; mt < 4; mt++) {
                    mma_bf16(acc[mt][nt], ah[mt], bh);
                    mma_bf16(acc[mt][nt], ah[mt], bl);
                    mma_bf16(acc[mt][nt], al[mt], bh);
                }
            }
        }

        if (s + 1 < NS) {
            uint32_t* dst = gsm + ((s + 1) & 1) * GSTG;
            uint32_t hi[4], lo[4];
            split8(ar0, ar1, hi, lo);
            *(uint4*)(dst + sto)     = *(uint4*)hi;
            *(uint4*)(dst + sto + 8) = *(uint4*)lo;
            split8(br0, br1, hi, lo);
            *(uint4*)(dst + GTILE + sto)     = *(uint4*)hi;
            *(uint4*)(dst + GTILE + sto + 8) = *(uint4*)lo;
            __syncthreads();
        }
    }

    // epilogue: c0,c1 -> (row g, col 2t4..), c2,c3 -> (row g+8)
    #pragma unroll
    for (int mt = 0; mt < 4; mt++) {
        const int row = bm + wr * 64 + mt * 16 + g;
        #pragma unroll
        for (int nt = 0; nt < 4; nt++) {
            const int col = bn + wc * 32 + nt * 8 + t4 * 2;
            const float b0 = bias[col], b1 = bias[col + 1];
            float2 lo, hi;
            lo.x = acc[mt][nt][0] + b0; lo.y = acc[mt][nt][1] + b1;
            hi.x = acc[mt][nt][2] + b0; hi.y = acc[mt][nt][3] + b1;
            *(float2*)&C[(long)row * N + col]       = lo;
            *(float2*)&C[(long)(row + 8) * N + col] = hi;
        }
    }
}

// ---------------------------------------------------------------------------
// MQA causal flash attention, bf16-split HMMA (unchanged from R5).
// ---------------------------------------------------------------------------
#define QP 132

__global__ void __launch_bounds__(128) mqa_flash_hmma(
    const float* __restrict__ qkv, float* __restrict__ attn_out)
{
    extern __shared__ uint32_t asm_[];
    uint32_t* q_s = asm_;                 // [64][QP]
    uint32_t* k_s = q_s + 64 * QP;
    uint32_t* v_s = k_s + 64 * QP;

    const int h  = blockIdx.y;
    const int bq = blockIdx.x;
    const int q0 = bq * 64;
    const int tid = threadIdx.x;
    const int wid = tid >> 5, lid = tid & 31;
    const int g = lid >> 2, t4 = lid & 3;

    const uint32_t v_base = smem_u32(v_s);

    const int lr  = tid >> 1;            // row 0..63
    const int lc0 = (tid & 1) * 16;      // chunk base 0 or 16

    // Load Q tile (pre-scaled by 1/sqrt(128)), split into hi/lo bf16.
    {
        const float* src = qkv + (long)(q0 + lr) * QKV_OUT + h * HD;
        uint32_t* dst = q_s + lr * QP;
        #pragma unroll
        for (int jj = 0; jj < 4; jj++) {
            const int c16 = lc0 + 32 * jj;   // covers d = 0..127
            split16(src + c16, dst + (c16 >> 1), dst + (c16 >> 1) + 64,
                    0.08838834764831845f);
        }
    }

    float o[16][4];
    #pragma unroll
    for (int i = 0; i < 16; i++)
        #pragma unroll
        for (int j = 0; j < 4; j++) o[i][j] = 0.0f;
    float m0 = -1e30f, m1 = -1e30f, l0 = 0.0f, l1 = 0.0f;

    const int row0 = q0 + wid * 16 + g;
    const int row1 = row0 + 8;

    for (int kt = 0; kt <= bq; kt++) {
        __syncthreads();   // Q ready / previous-iter smem reads done
        {
            const float* kp = qkv + (long)(kt * 64 + lr) * QKV_OUT + HID;
            uint32_t* kd = k_s + lr * QP;
            uint32_t* vd = v_s + lr * QP;
            #pragma unroll
            for (int jj = 0; jj < 4; jj++) {
                const int c16 = lc0 + 32 * jj;
                split16(kp + c16,      kd + (c16 >> 1), kd + (c16 >> 1) + 64, 1.0f);
                split16(kp + HD + c16, vd + (c16 >> 1), vd + (c16 >> 1) + 64, 1.0f);
            }
        }
        __syncthreads();

        // ---- S = Q K^T (3-term bf16) ----
        float s[8][4];
        #pragma unroll
        for (int nt = 0; nt < 8; nt++)
            #pragma unroll
            for (int j = 0; j < 4; j++) s[nt][j] = 0.0f;

        const uint32_t* qb = q_s + (wid * 16) * QP;
        #pragma unroll
        for (int ks = 0; ks < 8; ks++) {
            uint32_t ah[4], al[4];
            const int ro = g * QP + ks * 8 + t4;
            ah[0] = qb[ro];          ah[1] = qb[ro + 8 * QP];
            ah[2] = qb[ro + 4];      ah[3] = qb[ro + 8 * QP + 4];
            al[0] = qb[ro + 64];     al[1] = qb[ro + 8 * QP + 64];
            al[2] = qb[ro + 68];     al[3] = qb[ro + 8 * QP + 68];
            #pragma unroll
            for (int nt = 0; nt < 8; nt++) {
                const int rb = (nt * 8 + g) * QP + ks * 8 + t4;
                uint32_t bh[2] = { k_s[rb],      k_s[rb + 4]  };
                uint32_t bl[2] = { k_s[rb + 64], k_s[rb + 68] };
                mma_bf16(s[nt], ah, bh);
                mma_bf16(s[nt], ah, bl);
                mma_bf16(s[nt], al, bh);
            }
        }

        // causal mask (diagonal tile only)
        if (kt == bq) {
            #pragma unroll
            for (int nt = 0; nt < 8; nt++) {
                const int col = kt * 64 + nt * 8 + 2 * t4;
                if (col     > row0) s[nt][0] = -1e30f;
                if (col + 1 > row0) s[nt][1] = -1e30f;
                if (col     > row1) s[nt][2] = -1e30f;
                if (col + 1 > row1) s[nt][3] = -1e30f;
            }
        }

        // ---- online softmax (rows g and g+8) ----
        float mt0 = -1e30f, mt1 = -1e30f;
        #pragma unroll
        for (int nt = 0; nt < 8; nt++) {
            mt0 = fmaxf(mt0, fmaxf(s[nt][0], s[nt][1]));
            mt1 = fmaxf(mt1, fmaxf(s[nt][2], s[nt][3]));
        }
        mt0 = fmaxf(mt0, __shfl_xor_sync(0xffffffffu, mt0, 1));
        mt0 = fmaxf(mt0, __shfl_xor_sync(0xffffffffu, mt0, 2));
        mt1 = fmaxf(mt1, __shfl_xor_sync(0xffffffffu, mt1, 1));
        mt1 = fmaxf(mt1, __shfl_xor_sync(0xffffffffu, mt1, 2));

        const float mn0 = fmaxf(m0, mt0), mn1 = fmaxf(m1, mt1);
        const float al0 = __expf(m0 - mn0), al1 = __expf(m1 - mn1);

        float ps0 = 0.0f, ps1 = 0.0f;
        #pragma unroll
        for (int nt = 0; nt < 8; nt++) {
            s[nt][0] = __expf(s[nt][0] - mn0);
            s[nt][1] = __expf(s[nt][1] - mn0);
            s[nt][2] = __expf(s[nt][2] - mn1);
            s[nt][3] = __expf(s[nt][3] - mn1);
            ps0 += s[nt][0] + s[nt][1];
            ps1 += s[nt][2] + s[nt][3];
        }
        ps0 += __shfl_xor_sync(0xffffffffu, ps0, 1);
        ps0 += __shfl_xor_sync(0xffffffffu, ps0, 2);
        ps1 += __shfl_xor_sync(0xffffffffu, ps1, 1);
        ps1 += __shfl_xor_sync(0xffffffffu, ps1, 2);
        l0 = l0 * al0 + ps0; m0 = mn0;
        l1 = l1 * al1 + ps1; m1 = mn1;

        #pragma unroll
        for (int nt = 0; nt < 16; nt++) {
            o[nt][0] *= al0; o[nt][1] *= al0;
            o[nt][2] *= al1; o[nt][3] *= al1;
        }

        // ---- O += P V (3-term bf16); P frags packed directly from S frags ----
        #pragma unroll
        for (int jj = 0; jj < 4; jj++) {
            uint32_t ph[4], pl[4];
            pack_split2(s[2*jj][0],   s[2*jj][1],   ph[0], pl[0]);
            pack_split2(s[2*jj][2],   s[2*jj][3],   ph[1], pl[1]);
            pack_split2(s[2*jj+1][0], s[2*jj+1][1], ph[2], pl[2]);
            pack_split2(s[2*jj+1][2], s[2*jj+1][3], ph[3], pl[3]);

            const uint32_t rowaddr = v_base + (uint32_t)(((jj * 16 + (lid & 15)) * QP) * 4);
            #pragma unroll
            for (int nt = 0; nt < 16; nt++) {
                uint32_t bh[2], bl[2];
                ldsm_x2_t(bh[0], bh[1], rowaddr + nt * 16);
                ldsm_x2_t(bl[0], bl[1], rowaddr + 256 + nt * 16);
                mma_bf16(o[nt], ph, bh);
                mma_bf16(o[nt], ph, bl);
                mma_bf16(o[nt], pl, bh);
            }
        }
    }

    // epilogue
    const float i0 = 1.0f / l0, i1 = 1.0f / l1;
    #pragma unroll
    for (int nt = 0; nt < 16; nt++) {
        const int d = nt * 8 + 2 * t4;
        float2 a, b;
        a.x = o[nt][0] * i0; a.y = o[nt][1] * i0;
        b.x = o[nt][2] * i1; b.y = o[nt][3] * i1;
        *(float2*)&attn_out[(long)row0 * HID + h * HD + d] = a;
        *(float2*)&attn_out[(long)row1 * HID + h * HD + d] = b;
    }
}

// ---------------------------------------------------------------------------
extern "C" void kernel_launch(void* const* d_in, const int* in_sizes, int n_in,
                              void* d_out, int out_size)
{
    const float* x    = (const float*)d_in[0];
    const float* wqkv = (const float*)d_in[1];
    const float* bqkv = (const float*)d_in[2];
    const float* wo   = (const float*)d_in[3];
    const float* bo   = (const float*)d_in[4];
    float* out = (float*)d_out;

    float *qkv_buf, *attn_buf;
    cudaGetSymbolAddress((void**)&qkv_buf,  g_qkv);
    cudaGetSymbolAddress((void**)&attn_buf, g_attn);

    const int gemm_smem = 2 * GSTG * sizeof(uint32_t);     // 40960
    cudaFuncSetAttribute(gemm_bf16s,
                         cudaFuncAttributeMaxDynamicSharedMemorySize, gemm_smem);

    const int attn_smem = 3 * 64 * QP * sizeof(uint32_t);  // 101376
    cudaFuncSetAttribute(mqa_flash_hmma,
                         cudaFuncAttributeMaxDynamicSharedMemorySize, attn_smem);

    // 1) QKV projection
    {
        dim3 grid(QKV_OUT / 128, S_LEN / 128);
        gemm_bf16s<<<grid, 256, gemm_smem>>>(x, wqkv, bqkv, qkv_buf,
                                             S_LEN, QKV_OUT, HID);
    }
    // 2) attention
    {
        dim3 grid(S_LEN / 64, NH);
        mqa_flash_hmma<<<grid, 128, attn_smem>>>(qkv_buf, attn_buf);
    }
    // 3) output projection
    {
        dim3 grid(HID / 128, S_LEN / 128);
        gemm_bf16s<<<grid, 256, gemm_smem>>>(attn_buf, wo, bo, out,
                                             S_LEN, HID, HID);
    }
}